// round 13
// baseline (speedup 1.0000x reference)
#include <cuda_runtime.h>
#include <math.h>
#include <stdint.h>

#define EPS      1e-8f
#define THREADS  128
#define TILE     256     // rows per tile (2 rows per thread)
#define NC       4       // chunks per batch row
#define CHUNK    1024    // rows per CTA (S / NC)
#define NT       (CHUNK / TILE)   // 4 tiles per CTA
#define XSTRIDE  33      // floats per row in smem (conflict-free scalar access)

typedef unsigned long long ull;

// chunk partial exp-sums: partial[b*NC + c] = sum_{s in chunk} exp(att-1)
__device__ float g_partial[512 * NC];

// ---- packed f32x2 helpers (sm_103a FFMA2, PTX-only) ----
__device__ __forceinline__ ull pack2(float lo, float hi) {
    ull r; asm("mov.b64 %0, {%1, %2};" : "=l"(r) : "f"(lo), "f"(hi)); return r;
}
__device__ __forceinline__ void unpack2(ull v, float& lo, float& hi) {
    asm("mov.b64 {%0, %1}, %2;" : "=f"(lo), "=f"(hi) : "l"(v));
}
__device__ __forceinline__ ull ffma2(ull a, ull b, ull c) {
    ull d; asm("fma.rn.f32x2 %0, %1, %2, %3;" : "=l"(d) : "l"(a), "l"(b), "l"(c)); return d;
}
// volatile W loads: prevent hoisting W into registers across the tile loop
__device__ __forceinline__ void lds_w2(uint32_t addr, ull& a, ull& b) {
    asm volatile("ld.shared.v2.u64 {%0, %1}, [%2];" : "=l"(a), "=l"(b) : "r"(addr));
}
// 4-byte cp.async: gmem -> smem direct, keeps XSTRIDE=33 scalar layout
__device__ __forceinline__ void cp_async4(uint32_t saddr, const float* gptr) {
    asm volatile("cp.async.ca.shared.global [%0], [%1], 4;" :: "r"(saddr), "l"(gptr));
}
__device__ __forceinline__ void cp_commit() {
    asm volatile("cp.async.commit_group;" ::: "memory");
}
template <int N>
__device__ __forceinline__ void cp_wait() {
    asm volatile("cp.async.wait_group %0;" :: "n"(N) : "memory");
}

// stage one 256-row tile: warp w, step k copies row (w + 4k), lane l = col l.
// gmem: 128B contiguous per warp-step. smem bank = (row + l) % 32: conflict-free.
__device__ __forceinline__ void stage_tile(const float* __restrict__ g,
                                           uint32_t sbase, int w, int l) {
    #pragma unroll
    for (int k = 0; k < 64; k++) {
        int row = w + 4 * k;
        cp_async4(sbase + (uint32_t)(row * XSTRIDE + l) * 4, g + row * 32 + l);
    }
}

// smem: 2 tile buffers + W pairs + bq/kn pairs + misc
#define XBUF_FLOATS (TILE * XSTRIDE)
#define SMEM_BYTES  (2 * XBUF_FLOATS * 4 + 256 * 8 + 16 * 8 + 24 * 4)

// Pass 1: CTA (b,c) -> rows [c*CHUNK, (c+1)*CHUNK). cp.async double-buffered.
// att <= 1 (cosine), so exp-shift is the constant 1: no max pass needed.
__global__ __launch_bounds__(THREADS, 3) void attn_cosine_pass1(
    const float* __restrict__ dec,   // [B,32]
    const float* __restrict__ enc,   // [B,S,32]
    const float* __restrict__ Wq,    // [16,32]
    const float* __restrict__ bq,    // [16]
    const float* __restrict__ Wk,    // [16,32]
    const float* __restrict__ bk,    // [16]
    float* __restrict__ out,         // [B,S]
    int S)
{
    extern __shared__ float smem[];
    float* s_x0    = smem;                       // buffer 0
    float* s_x1    = smem + XBUF_FLOATS;         // buffer 1
    ull*   s_W     = (ull*)(smem + 2 * XBUF_FLOATS); // 256 ull, 16B aligned
    ull*   s_bqp   = s_W + 256;
    ull*   s_knp   = s_bqp + 8;
    float* s_kvec  = (float*)(s_knp + 8);
    float* s_red   = s_kvec + 16;

    const int b   = blockIdx.x >> 2;       // NC = 4
    const int c   = blockIdx.x & (NC - 1);
    const int tid = threadIdx.x;
    const int w   = tid >> 5, l = tid & 31;

    const int row0 = c * CHUNK;
    const float* encb = enc + (size_t)b * S * 32 + (size_t)row0 * 32;
    const uint32_t x0a = (uint32_t)__cvta_generic_to_shared(s_x0);
    const uint32_t x1a = (uint32_t)__cvta_generic_to_shared(s_x1);

    // prefetch tile 0 immediately (overlaps with setup below)
    stage_tile(encb, x0a, w, l);
    cp_commit();

    // ---- setup: W d-pairs (h-major), bq pairs, k projection ----
    #pragma unroll
    for (int e = tid; e < 256; e += THREADS) {
        int h = e >> 3, dd = e & 7;
        s_W[h * 8 + dd] = pack2(Wq[(2 * dd) * 32 + h], Wq[(2 * dd + 1) * 32 + h]);
    }
    if (tid < 8) s_bqp[tid] = pack2(bq[2 * tid], bq[2 * tid + 1]);
    if (tid < 16) {
        float kd = bk[tid];
        const float* wr = Wk + tid * 32;
        const float* xr = dec + b * 32;
        #pragma unroll
        for (int h = 0; h < 32; h++) kd = fmaf(wr[h], xr[h], kd);
        s_kvec[tid] = kd;
    }
    __syncthreads();
    if (tid < 8) {
        float ss = 0.f;
        #pragma unroll
        for (int d = 0; d < 16; d++) { float v = s_kvec[d]; ss = fmaf(v, v, ss); }
        float inv = 1.0f / fmaxf(sqrtf(ss), EPS);
        s_knp[tid] = pack2(s_kvec[2 * tid] * inv, s_kvec[2 * tid + 1] * inv);
    }

    float* ob = out + (size_t)b * S + row0;
    const uint32_t wbase = (uint32_t)__cvta_generic_to_shared(s_W);
    float lsum = 0.f;

    // ---- pipelined tiles ----
    #pragma unroll 1
    for (int t = 0; t < NT; t++) {
        // prefetch next tile into the other buffer (its previous consumer
        // finished at the trailing __syncthreads of iteration t-1)
        if (t + 1 < NT) {
            stage_tile(encb + (t + 1) * TILE * 32, (t + 1) & 1 ? x1a : x0a, w, l);
            cp_commit();
            cp_wait<1>();     // current tile's group has landed
        } else {
            cp_wait<0>();
        }
        __syncthreads();      // all threads' cp.async visible + s_knp/s_W on t=0

        const float* s_x = (t & 1) ? s_x1 : s_x0;
        const int base = t * TILE;

        // compute: rows (tid) and (tid+128) share every W load
        {
            const float* xr0 = s_x + tid * XSTRIDE;
            const float* xr1 = s_x + (tid + 128) * XSTRIDE;
            ull acc0[8], acc1[8];
            #pragma unroll
            for (int j = 0; j < 8; j++) { acc0[j] = s_bqp[j]; acc1[j] = s_bqp[j]; }

            #pragma unroll 4
            for (int h = 0; h < 32; h++) {
                float xv0 = xr0[h];          // bank (tid+h)%32: conflict-free
                float xv1 = xr1[h];
                ull xp0 = pack2(xv0, xv0);
                ull xp1 = pack2(xv1, xv1);
                uint32_t wa = wbase + (uint32_t)h * 64;
                ull w0, w1, w2, w3, w4, w5, w6, w7;
                lds_w2(wa,      w0, w1);     // broadcast LDS.128
                lds_w2(wa + 16, w2, w3);
                lds_w2(wa + 32, w4, w5);
                lds_w2(wa + 48, w6, w7);
                acc0[0] = ffma2(xp0, w0, acc0[0]);  acc1[0] = ffma2(xp1, w0, acc1[0]);
                acc0[1] = ffma2(xp0, w1, acc0[1]);  acc1[1] = ffma2(xp1, w1, acc1[1]);
                acc0[2] = ffma2(xp0, w2, acc0[2]);  acc1[2] = ffma2(xp1, w2, acc1[2]);
                acc0[3] = ffma2(xp0, w3, acc0[3]);  acc1[3] = ffma2(xp1, w3, acc1[3]);
                acc0[4] = ffma2(xp0, w4, acc0[4]);  acc1[4] = ffma2(xp1, w4, acc1[4]);
                acc0[5] = ffma2(xp0, w5, acc0[5]);  acc1[5] = ffma2(xp1, w5, acc1[5]);
                acc0[6] = ffma2(xp0, w6, acc0[6]);  acc1[6] = ffma2(xp1, w6, acc1[6]);
                acc0[7] = ffma2(xp0, w7, acc0[7]);  acc1[7] = ffma2(xp1, w7, acc1[7]);
            }

            ull ssp0 = 0ull, dpp0 = 0ull, ssp1 = 0ull, dpp1 = 0ull;
            #pragma unroll
            for (int j = 0; j < 8; j++) {
                ull knj = s_knp[j];
                ssp0 = ffma2(acc0[j], acc0[j], ssp0);
                dpp0 = ffma2(acc0[j], knj,    dpp0);
                ssp1 = ffma2(acc1[j], acc1[j], ssp1);
                dpp1 = ffma2(acc1[j], knj,    dpp1);
            }
            float sa, sb, da, db;
            unpack2(ssp0, sa, sb); unpack2(dpp0, da, db);
            float att0 = (da + db) / fmaxf(sqrtf(sa + sb), EPS);
            unpack2(ssp1, sa, sb); unpack2(dpp1, da, db);
            float att1 = (da + db) / fmaxf(sqrtf(sa + sb), EPS);
            ob[base + tid]       = att0;      // coalesced direct store
            ob[base + tid + 128] = att1;
            lsum += __expf(att0 - 1.0f) + __expf(att1 - 1.0f);
        }
        __syncthreads();      // buffer free for the next prefetch
    }

    // ---- block reduce exp-sum -> g_partial ----
    #pragma unroll
    for (int o = 16; o; o >>= 1)
        lsum += __shfl_xor_sync(0xFFFFFFFFu, lsum, o);
    if ((tid & 31) == 0) s_red[tid >> 5] = lsum;
    __syncthreads();
    if (tid == 0)
        g_partial[b * NC + c] = s_red[0] + s_red[1] + s_red[2] + s_red[3];
}

// Pass 2: per batch row, combine NC partials -> lse, subtract (float4 sweep).
__global__ __launch_bounds__(256) void attn_cosine_pass2(
    float* __restrict__ out, int S)
{
    __shared__ float s_lse;
    const int b   = blockIdx.x;
    const int tid = threadIdx.x;

    if (tid == 0) {
        float s = 0.f;
        #pragma unroll
        for (int c = 0; c < NC; c++) s += g_partial[b * NC + c];
        s_lse = 1.0f + logf(s);
    }
    __syncthreads();
    const float lse = s_lse;

    float4* o4 = reinterpret_cast<float4*>(out + (size_t)b * S);
    const int n4 = S / 4;
    #pragma unroll
    for (int i = tid; i < n4; i += 256) {
        float4 v = o4[i];
        v.x -= lse; v.y -= lse; v.z -= lse; v.w -= lse;
        o4[i] = v;
    }
}

extern "C" void kernel_launch(void* const* d_in, const int* in_sizes, int n_in,
                              void* d_out, int out_size) {
    const float* dec = (const float*)d_in[0];   // [B,32]
    const float* enc = (const float*)d_in[1];   // [B,S,32]
    const float* Wq  = (const float*)d_in[2];   // [16,32]
    const float* bq  = (const float*)d_in[3];   // [16]
    const float* Wk  = (const float*)d_in[4];   // [16,32]
    const float* bk  = (const float*)d_in[5];   // [16]
    float* out = (float*)d_out;

    const int H = 32;
    const int B = in_sizes[0] / H;                 // 512
    const int S = in_sizes[1] / (B * H);           // 4096

    cudaFuncSetAttribute(attn_cosine_pass1,
                         cudaFuncAttributeMaxDynamicSharedMemorySize, SMEM_BYTES);
    attn_cosine_pass1<<<B * NC, THREADS, SMEM_BYTES>>>(dec, enc, Wq, bq, Wk, bk, out, S);
    attn_cosine_pass2<<<B, 256>>>(out, S);
}

// round 15
// speedup vs baseline: 1.4259x; 1.4259x over previous
#include <cuda_runtime.h>
#include <math.h>
#include <stdint.h>

#define EPS      1e-8f
#define THREADS  128
#define TILE     256     // rows per tile (2 rows per thread)
#define NC       4       // chunks per batch row
#define CHUNK    1024    // rows per CTA (S / NC)
#define NT       (CHUNK / TILE)   // 4 tiles per CTA

typedef unsigned long long ull;

// chunk partial exp-sums: partial[b*NC + c] = sum_{s in chunk} exp(att-1)
__device__ float g_partial[512 * NC];

// ---- packed f32x2 helpers (sm_103a FFMA2, PTX-only) ----
__device__ __forceinline__ ull pack2(float lo, float hi) {
    ull r; asm("mov.b64 %0, {%1, %2};" : "=l"(r) : "f"(lo), "f"(hi)); return r;
}
__device__ __forceinline__ void unpack2(ull v, float& lo, float& hi) {
    asm("mov.b64 {%0, %1}, %2;" : "=f"(lo), "=f"(hi) : "l"(v));
}
__device__ __forceinline__ ull ffma2(ull a, ull b, ull c) {
    ull d; asm("fma.rn.f32x2 %0, %1, %2, %3;" : "=l"(d) : "l"(a), "l"(b), "l"(c)); return d;
}
// volatile W loads: prevent hoisting W into registers across the tile loop
__device__ __forceinline__ void lds_w2(uint32_t addr, ull& a, ull& b) {
    asm volatile("ld.shared.v2.u64 {%0, %1}, [%2];" : "=l"(a), "=l"(b) : "r"(addr));
}
__device__ __forceinline__ void lds128(uint32_t addr, float4& v) {
    asm volatile("ld.shared.v4.f32 {%0, %1, %2, %3}, [%4];"
                 : "=f"(v.x), "=f"(v.y), "=f"(v.z), "=f"(v.w) : "r"(addr));
}
// 16-byte cp.async (cg = L1 bypass): one instr moves 512B per warp
__device__ __forceinline__ void cp_async16(uint32_t saddr, const float* gptr) {
    asm volatile("cp.async.cg.shared.global [%0], [%1], 16;" :: "r"(saddr), "l"(gptr));
}
__device__ __forceinline__ void cp_commit() {
    asm volatile("cp.async.commit_group;" ::: "memory");
}
template <int N>
__device__ __forceinline__ void cp_wait() {
    asm volatile("cp.async.wait_group %0;" :: "n"(N) : "memory");
}

// XOR-swizzled tile: row stride 128B, chunk hh stored at column (hh ^ (row & 7)).
// stage: 2048 16B-chunks, 16 per thread; gmem 512B-contiguous per warp instr,
// smem STS phase = 1 row x 8 distinct swizzled columns: conflict-free.
__device__ __forceinline__ void stage_tile(const float* __restrict__ g,
                                           uint32_t sbase, int tid) {
    #pragma unroll
    for (int k = 0; k < 16; k++) {
        int L = tid + k * THREADS;
        int row = L >> 3, hh = L & 7;
        uint32_t dst = sbase + (uint32_t)(row * 128 + ((hh ^ (row & 7)) << 4));
        cp_async16(dst, g + row * 32 + hh * 4);
    }
}

// smem: 2 x 32KB tile buffers + W pairs + bq/kn pairs + misc
#define XBUF_BYTES (TILE * 128)
#define SMEM_BYTES (2 * XBUF_BYTES + 256 * 8 + 16 * 8 + 24 * 4)

// Pass 1: CTA (b,c) -> rows [c*CHUNK, (c+1)*CHUNK). cp.async.16 double-buffered.
// att <= 1 (cosine), so exp-shift is the constant 1: no max pass needed.
__global__ __launch_bounds__(THREADS, 3) void attn_cosine_pass1(
    const float* __restrict__ dec,   // [B,32]
    const float* __restrict__ enc,   // [B,S,32]
    const float* __restrict__ Wq,    // [16,32]
    const float* __restrict__ bq,    // [16]
    const float* __restrict__ Wk,    // [16,32]
    const float* __restrict__ bk,    // [16]
    float* __restrict__ out,         // [B,S]
    int S)
{
    extern __shared__ float smem[];
    float* s_x0    = smem;                            // buffer 0 (32 KB)
    float* s_x1    = smem + XBUF_BYTES / 4;           // buffer 1
    ull*   s_W     = (ull*)(smem + 2 * (XBUF_BYTES / 4)); // 256 ull, 16B aligned
    ull*   s_bqp   = s_W + 256;
    ull*   s_knp   = s_bqp + 8;
    float* s_kvec  = (float*)(s_knp + 8);
    float* s_red   = s_kvec + 16;

    const int b   = blockIdx.x >> 2;       // NC = 4
    const int c   = blockIdx.x & (NC - 1);
    const int tid = threadIdx.x;

    const int row0 = c * CHUNK;
    const float* encb = enc + (size_t)b * S * 32 + (size_t)row0 * 32;
    const uint32_t x0a = (uint32_t)__cvta_generic_to_shared(s_x0);
    const uint32_t x1a = (uint32_t)__cvta_generic_to_shared(s_x1);

    // prefetch tile 0 immediately (overlaps with setup below)
    stage_tile(encb, x0a, tid);
    cp_commit();

    // ---- setup: W d-pairs (h-major), bq pairs, k projection ----
    #pragma unroll
    for (int e = tid; e < 256; e += THREADS) {
        int h = e >> 3, dd = e & 7;
        s_W[h * 8 + dd] = pack2(Wq[(2 * dd) * 32 + h], Wq[(2 * dd + 1) * 32 + h]);
    }
    if (tid < 8) s_bqp[tid] = pack2(bq[2 * tid], bq[2 * tid + 1]);
    if (tid < 16) {
        float kd = bk[tid];
        const float* wr = Wk + tid * 32;
        const float* xr = dec + b * 32;
        #pragma unroll
        for (int h = 0; h < 32; h++) kd = fmaf(wr[h], xr[h], kd);
        s_kvec[tid] = kd;
    }
    __syncthreads();
    if (tid < 8) {
        float ss = 0.f;
        #pragma unroll
        for (int d = 0; d < 16; d++) { float v = s_kvec[d]; ss = fmaf(v, v, ss); }
        float inv = 1.0f / fmaxf(sqrtf(ss), EPS);
        s_knp[tid] = pack2(s_kvec[2 * tid] * inv, s_kvec[2 * tid + 1] * inv);
    }

    float* ob = out + (size_t)b * S + row0;
    const uint32_t wbase = (uint32_t)__cvta_generic_to_shared(s_W);
    // swizzled x addresses for this thread's two rows (row0 = tid, row1 = tid+128)
    const int sw0 = tid & 7, sw1 = (tid + 128) & 7;
    float lsum = 0.f;

    // ---- pipelined tiles ----
    #pragma unroll 1
    for (int t = 0; t < NT; t++) {
        if (t + 1 < NT) {
            stage_tile(encb + (t + 1) * TILE * 32, ((t + 1) & 1) ? x1a : x0a, tid);
            cp_commit();
            cp_wait<1>();     // current tile's group has landed
        } else {
            cp_wait<0>();
        }
        __syncthreads();      // cp.async visible to all + s_knp/s_W on t=0

        const uint32_t xa = (t & 1) ? x1a : x0a;
        const uint32_t xr0 = xa + (uint32_t)tid * 128;
        const uint32_t xr1 = xa + (uint32_t)(tid + 128) * 128;
        const int base = t * TILE;

        // compute: rows (tid) and (tid+128) share every W load
        {
            ull acc0[8], acc1[8];
            #pragma unroll
            for (int j = 0; j < 8; j++) { acc0[j] = s_bqp[j]; acc1[j] = s_bqp[j]; }

            #pragma unroll
            for (int hh = 0; hh < 8; hh++) {
                float4 v0, v1;
                lds128(xr0 + (uint32_t)((hh ^ sw0) << 4), v0);  // phase-conflict-free
                lds128(xr1 + (uint32_t)((hh ^ sw1) << 4), v1);
                float a0[4] = {v0.x, v0.y, v0.z, v0.w};
                float a1[4] = {v1.x, v1.y, v1.z, v1.w};
                #pragma unroll
                for (int j = 0; j < 4; j++) {
                    int h = hh * 4 + j;
                    ull xp0 = pack2(a0[j], a0[j]);
                    ull xp1 = pack2(a1[j], a1[j]);
                    uint32_t wa = wbase + (uint32_t)h * 64;
                    ull w0, w1, w2, w3, w4, w5, w6, w7;
                    lds_w2(wa,      w0, w1);     // broadcast LDS.128
                    lds_w2(wa + 16, w2, w3);
                    lds_w2(wa + 32, w4, w5);
                    lds_w2(wa + 48, w6, w7);
                    acc0[0] = ffma2(xp0, w0, acc0[0]);  acc1[0] = ffma2(xp1, w0, acc1[0]);
                    acc0[1] = ffma2(xp0, w1, acc0[1]);  acc1[1] = ffma2(xp1, w1, acc1[1]);
                    acc0[2] = ffma2(xp0, w2, acc0[2]);  acc1[2] = ffma2(xp1, w2, acc1[2]);
                    acc0[3] = ffma2(xp0, w3, acc0[3]);  acc1[3] = ffma2(xp1, w3, acc1[3]);
                    acc0[4] = ffma2(xp0, w4, acc0[4]);  acc1[4] = ffma2(xp1, w4, acc1[4]);
                    acc0[5] = ffma2(xp0, w5, acc0[5]);  acc1[5] = ffma2(xp1, w5, acc1[5]);
                    acc0[6] = ffma2(xp0, w6, acc0[6]);  acc1[6] = ffma2(xp1, w6, acc1[6]);
                    acc0[7] = ffma2(xp0, w7, acc0[7]);  acc1[7] = ffma2(xp1, w7, acc1[7]);
                }
            }

            ull ssp0 = 0ull, dpp0 = 0ull, ssp1 = 0ull, dpp1 = 0ull;
            #pragma unroll
            for (int j = 0; j < 8; j++) {
                ull knj = s_knp[j];
                ssp0 = ffma2(acc0[j], acc0[j], ssp0);
                dpp0 = ffma2(acc0[j], knj,    dpp0);
                ssp1 = ffma2(acc1[j], acc1[j], ssp1);
                dpp1 = ffma2(acc1[j], knj,    dpp1);
            }
            float sa, sb, da, db;
            unpack2(ssp0, sa, sb); unpack2(dpp0, da, db);
            float att0 = (da + db) / fmaxf(sqrtf(sa + sb), EPS);
            unpack2(ssp1, sa, sb); unpack2(dpp1, da, db);
            float att1 = (da + db) / fmaxf(sqrtf(sa + sb), EPS);
            ob[base + tid]       = att0;      // coalesced direct store
            ob[base + tid + 128] = att1;
            lsum += __expf(att0 - 1.0f) + __expf(att1 - 1.0f);
        }
        __syncthreads();      // buffer free for the next prefetch
    }

    // ---- block reduce exp-sum -> g_partial ----
    #pragma unroll
    for (int o = 16; o; o >>= 1)
        lsum += __shfl_xor_sync(0xFFFFFFFFu, lsum, o);
    if ((tid & 31) == 0) s_red[tid >> 5] = lsum;
    __syncthreads();
    if (tid == 0)
        g_partial[b * NC + c] = s_red[0] + s_red[1] + s_red[2] + s_red[3];
}

// Pass 2: CTA (b,c) combines NC partials -> lse, subtracts over its own chunk.
__global__ __launch_bounds__(256) void attn_cosine_pass2(
    float* __restrict__ out, int S)
{
    __shared__ float s_lse;
    const int b   = blockIdx.x >> 2;
    const int c   = blockIdx.x & (NC - 1);
    const int tid = threadIdx.x;

    if (tid == 0) {
        float s = 0.f;
        #pragma unroll
        for (int k = 0; k < NC; k++) s += g_partial[b * NC + k];
        s_lse = 1.0f + logf(s);
    }
    __syncthreads();
    const float lse = s_lse;

    float4* o4 = reinterpret_cast<float4*>(out + (size_t)b * S + c * CHUNK);
    const int n4 = CHUNK / 4;    // 256 = one float4 per thread
    #pragma unroll
    for (int i = tid; i < n4; i += 256) {
        float4 v = o4[i];
        v.x -= lse; v.y -= lse; v.z -= lse; v.w -= lse;
        o4[i] = v;
    }
}

extern "C" void kernel_launch(void* const* d_in, const int* in_sizes, int n_in,
                              void* d_out, int out_size) {
    const float* dec = (const float*)d_in[0];   // [B,32]
    const float* enc = (const float*)d_in[1];   // [B,S,32]
    const float* Wq  = (const float*)d_in[2];   // [16,32]
    const float* bq  = (const float*)d_in[3];   // [16]
    const float* Wk  = (const float*)d_in[4];   // [16,32]
    const float* bk  = (const float*)d_in[5];   // [16]
    float* out = (float*)d_out;

    const int H = 32;
    const int B = in_sizes[0] / H;                 // 512
    const int S = in_sizes[1] / (B * H);           // 4096

    cudaFuncSetAttribute(attn_cosine_pass1,
                         cudaFuncAttributeMaxDynamicSharedMemorySize, SMEM_BYTES);
    attn_cosine_pass1<<<B * NC, THREADS, SMEM_BYTES>>>(dec, enc, Wq, bq, Wk, bk, out, S);
    attn_cosine_pass2<<<B * NC, 256>>>(out, S);
}